// round 2
// baseline (speedup 1.0000x reference)
#include <cuda_runtime.h>
#include <cuda_fp16.h>
#include <mma.h>

using namespace nvcuda;

// Problem constants
#define BB   64      // batch
#define TT   512     // time steps
#define KK   512     // IN == H
#define G3   1536    // 3*H
#define NLAYER 2

// Partition constants
#define NC   32      // column-CTAs per (layer, batch-group)
#define NB   2       // batch groups
#define BC   32      // batch rows per group (BB/NB)
#define HC   16      // H columns per CTA (KK/NC)
#define LDB  520     // padded smem weight row stride (halves)
#define NWARP 12
#define NTHREADS 384

// ---------------- persistent device scratch (no cudaMalloc allowed) ----------
__device__ __half g_x_hi[(size_t)BB * TT * KK];   // 32 MB
__device__ __half g_x_lo[(size_t)BB * TT * KK];   // 32 MB
__device__ __half g_h_hi[NLAYER][2][BB * KK];     // [layer][parity][b*K]
__device__ __half g_h_lo[NLAYER][2][BB * KK];
__device__ unsigned int g_cnt[NLAYER][NB];        // per-(layer,group) step counters

// ---------------- prepass: split x + encoder_h into fp16 hi/lo, reset counters
__global__ void gru_prepass(const float* __restrict__ x,
                            const float* __restrict__ enc) {
    size_t i = (size_t)blockIdx.x * blockDim.x + threadIdx.x;
    size_t stride = (size_t)gridDim.x * blockDim.x;
    size_t n = (size_t)BB * TT * KK;
    for (size_t idx = i; idx < n; idx += stride) {
        float v = x[idx];
        __half hi = __float2half_rn(v);
        g_x_hi[idx] = hi;
        g_x_lo[idx] = __float2half_rn(v - __half2float(hi));
    }
    size_t ne = (size_t)NLAYER * BB * KK;
    for (size_t idx = i; idx < ne; idx += stride) {
        int l = (int)(idx / (BB * KK));
        int r = (int)(idx % (BB * KK));
        float v = enc[idx];
        __half hi = __float2half_rn(v);
        g_h_hi[l][1][r] = hi;                       // parity 1 == h(t=-1)
        g_h_lo[l][1][r] = __float2half_rn(v - __half2float(hi));
    }
    if (i < NLAYER * NB) {
        ((unsigned int*)g_cnt)[i] = 0u;
    }
}

// ---------------- main persistent pipelined GRU kernel -----------------------
extern "C" __global__ void __launch_bounds__(NTHREADS, 1)
gru_main(const float* __restrict__ Wih, const float* __restrict__ Whh,
         const float* __restrict__ bih, const float* __restrict__ bhh,
         float* __restrict__ out) {
    extern __shared__ __half smem[];
    __half* sWih_hi = smem;                    // 48 x LDB
    __half* sWih_lo = smem + 1 * 48 * LDB;
    __half* sWhh_hi = smem + 2 * 48 * LDB;
    __half* sWhh_lo = smem + 3 * 48 * LDB;
    float*  stage   = (float*)(smem + 4 * 48 * LDB);  // 12 tiles of 16x20 fp32

    const int bid   = blockIdx.x;
    const int layer = bid >> 6;        // 0..1
    const int rem   = bid & 63;
    const int g     = rem >> 5;        // batch group 0..1
    const int cidx  = rem & 31;        // column CTA 0..31
    const int b0    = g * BC;
    const int tid   = threadIdx.x;
    const int wid   = tid >> 5;

    // ---- load + split this CTA's weight slice into SMEM (once) ----
    const float* WihL = Wih + (size_t)layer * G3 * KK;
    const float* WhhL = Whh + (size_t)layer * G3 * KK;
    for (int idx = tid; idx < 48 * KK; idx += NTHREADS) {
        int row = idx >> 9;            // 0..47 (gate*16 + r)
        int k   = idx & 511;
        int grow = (row >> 4) * 512 + cidx * 16 + (row & 15); // global gate row
        float v = WihL[(size_t)grow * KK + k];
        __half h = __float2half_rn(v);
        sWih_hi[row * LDB + k] = h;
        sWih_lo[row * LDB + k] = __float2half_rn(v - __half2float(h));
        v = WhhL[(size_t)grow * KK + k];
        h = __float2half_rn(v);
        sWhh_hi[row * LDB + k] = h;
        sWhh_lo[row * LDB + k] = __float2half_rn(v - __half2float(h));
    }
    __syncthreads();

    // job mapping: 12 warps = 2 row-blocks x {gi_r, gh_r, gi_z, gh_z, gi_n, gh_n}
    const int  rb    = wid / 6;        // 0..1 (16-row batch block)
    const int  jj    = wid % 6;
    const int  gate  = jj >> 1;        // 0=r 1=z 2=n
    const bool is_gi = (jj & 1) == 0;
    const __half* Bhi = (is_gi ? sWih_hi : sWhh_hi) + gate * 16 * LDB;
    const __half* Blo = (is_gi ? sWih_lo : sWhh_lo) + gate * 16 * LDB;

    volatile unsigned int* cnt0 = &g_cnt[0][g];
    volatile unsigned int* cnt1 = &g_cnt[1][g];

    // bias values for epilogue (cached per thread where used)
    for (int t = 0; t < TT; t++) {
        // ---- inter-CTA waits (producer/consumer + backpressure) ----
        if (tid == 0) {
            unsigned tgt0, tgt1;
            if (layer == 0) {
                tgt0 = (unsigned)(NC * t);                       // own layer done t-1
                tgt1 = (t >= 1) ? (unsigned)(NC * (t - 1)) : 0u; // layer1 done t-2
            } else {
                tgt0 = (unsigned)(NC * (t + 1));                 // h0(t) ready
                tgt1 = (unsigned)(NC * t);                       // own layer done t-1
            }
            while (*cnt0 < tgt0 || *cnt1 < tgt1) { __nanosleep(64); }
            __threadfence();
        }
        __syncthreads();

        // ---- A operand selection ----
        const __half *Ahi, *Alo;
        unsigned lda;
        if (layer == 0 && is_gi) {
            size_t off = ((size_t)b0 * TT + t) * KK;
            Ahi = g_x_hi + off;  Alo = g_x_lo + off;  lda = TT * KK;
        } else {
            int srcl = is_gi ? 0 : layer;                 // layer1 gi reads h0(t)
            int par  = is_gi ? (t & 1) : ((t + 1) & 1);   // gh reads h(t-1)
            Ahi = &g_h_hi[srcl][par][b0 * KK];
            Alo = &g_h_lo[srcl][par][b0 * KK];
            lda = KK;
        }
        Ahi += (size_t)rb * 16 * lda;
        Alo += (size_t)rb * 16 * lda;

        // ---- 3-pass fp16 GEMM: C[16x16] over K=512 ----
        wmma::fragment<wmma::accumulator, 16, 16, 16, float> acc;
        wmma::fill_fragment(acc, 0.0f);
        for (int k0 = 0; k0 < KK; k0 += 16) {
            wmma::fragment<wmma::matrix_a, 16, 16, 16, __half, wmma::row_major> ahi, alo;
            wmma::fragment<wmma::matrix_b, 16, 16, 16, __half, wmma::col_major> bhif, blof;
            wmma::load_matrix_sync(ahi,  Ahi + k0, lda);
            wmma::load_matrix_sync(alo,  Alo + k0, lda);
            wmma::load_matrix_sync(bhif, Bhi + k0, LDB);
            wmma::load_matrix_sync(blof, Blo + k0, LDB);
            wmma::mma_sync(acc, ahi, bhif, acc);   // hi*hi
            wmma::mma_sync(acc, alo, bhif, acc);   // lo*hi
            wmma::mma_sync(acc, ahi, blof, acc);   // hi*lo
        }
        wmma::store_matrix_sync(stage + wid * 16 * 20, acc, 20, wmma::mem_row_major);
        __syncthreads();

        // ---- epilogue: gates + state update for this CTA's 32x16 slice ----
        for (int e = tid; e < BC * HC; e += NTHREADS) {
            int row = e >> 4;            // 0..31 batch row in group
            int c   = e & 15;            // 0..15 local H col
            int rb2 = row >> 4;
            int rr  = row & 15;
            const float* st = stage + rb2 * 6 * 320;
            float giR = st[0 * 320 + rr * 20 + c];
            float ghR = st[1 * 320 + rr * 20 + c];
            float giZ = st[2 * 320 + rr * 20 + c];
            float ghZ = st[3 * 320 + rr * 20 + c];
            float giN = st[4 * 320 + rr * 20 + c];
            float ghN = st[5 * 320 + rr * 20 + c];

            int gc = cidx * 16 + c;                  // global H column
            const float* bihL = bih + layer * G3;
            const float* bhhL = bhh + layer * G3;
            float r = 1.0f / (1.0f + expf(-(giR + bihL[gc]        + ghR + bhhL[gc])));
            float z = 1.0f / (1.0f + expf(-(giZ + bihL[512 + gc]  + ghZ + bhhL[512 + gc])));
            float n = tanhf(giN + bihL[1024 + gc] + r * (ghN + bhhL[1024 + gc]));

            int hb = b0 + row;
            int pv = (t + 1) & 1;                    // parity of h(t-1)
            int hidx = hb * KK + gc;
            float hp = __half2float(g_h_hi[layer][pv][hidx]) +
                       __half2float(g_h_lo[layer][pv][hidx]);
            float hn = (1.0f - z) * n + z * hp;

            int pc = t & 1;                          // parity of h(t)
            __half hh = __float2half_rn(hn);
            g_h_hi[layer][pc][hidx] = hh;
            g_h_lo[layer][pc][hidx] = __float2half_rn(hn - __half2float(hh));

            if (layer == 1)
                out[((size_t)hb * TT + t) * KK + gc] = hn;
            if (t == TT - 1)
                out[(size_t)BB * TT * KK + (size_t)layer * BB * KK + hidx] = hn;
        }
        __threadfence();
        __syncthreads();
        if (tid == 0) {
            atomicAdd((unsigned int*)(layer == 0 ? cnt0 : cnt1), 1u);
        }
    }
}

// ---------------- launcher ---------------------------------------------------
extern "C" void kernel_launch(void* const* d_in, const int* in_sizes, int n_in,
                              void* d_out, int out_size) {
    const float* x   = (const float*)d_in[0];  // [B,T,IN]
    const float* enc = (const float*)d_in[1];  // [L,B,H]
    const float* Wih = (const float*)d_in[2];  // [L,3H,IN]
    const float* Whh = (const float*)d_in[3];  // [L,3H,H]
    const float* bih = (const float*)d_in[4];  // [L,3H]
    const float* bhh = (const float*)d_in[5];  // [L,3H]
    float* out = (float*)d_out;                // [B,T,H] ++ [L,B,H]

    (void)in_sizes; (void)n_in; (void)out_size;

    // 4 weight matrices split hi/lo + fp32 staging tiles
    size_t smem_bytes = (size_t)4 * 48 * LDB * sizeof(__half)
                      + (size_t)NWARP * 16 * 20 * sizeof(float); // 215,040 B
    cudaFuncSetAttribute(gru_main, cudaFuncAttributeMaxDynamicSharedMemorySize,
                         (int)smem_bytes);

    gru_prepass<<<2048, 256>>>(x, enc);
    gru_main<<<NLAYER * NC * NB, NTHREADS, smem_bytes>>>(Wih, Whh, bih, bhh, out);
}

// round 3
// speedup vs baseline: 1.0007x; 1.0007x over previous
#include <cuda_runtime.h>
#include <cuda_fp16.h>
#include <mma.h>

using namespace nvcuda;

// Problem constants
#define BB   64      // batch
#define TT   512     // time steps
#define KK   512     // IN == H
#define G3   1536    // 3*H
#define NLAYER 2

// Partition constants
#define NC   32      // column-CTAs per (layer, batch-group)
#define NB   2       // batch groups
#define BC   32      // batch rows per group (BB/NB)
#define HC   16      // H columns per CTA (KK/NC)
#define LDB  520     // padded smem weight row stride (halves)
#define NWARP 12
#define NTHREADS 384

// ---------------- persistent device scratch (no cudaMalloc allowed) ----------
__device__ __half g_x_hi[(size_t)BB * TT * KK];   // 32 MB
__device__ __half g_x_lo[(size_t)BB * TT * KK];   // 32 MB
__device__ __half g_h_hi[NLAYER][2][BB * KK];     // [layer][parity][b*K]
__device__ __half g_h_lo[NLAYER][2][BB * KK];
__device__ unsigned int g_cnt[NLAYER][NB];        // per-(layer,group) step counters

// ---------------- prepass: split x + encoder_h into fp16 hi/lo, reset counters
__global__ void gru_prepass(const float* __restrict__ x,
                            const float* __restrict__ enc) {
    size_t i = (size_t)blockIdx.x * blockDim.x + threadIdx.x;
    size_t stride = (size_t)gridDim.x * blockDim.x;
    size_t n = (size_t)BB * TT * KK;
    for (size_t idx = i; idx < n; idx += stride) {
        float v = x[idx];
        __half hi = __float2half_rn(v);
        g_x_hi[idx] = hi;
        g_x_lo[idx] = __float2half_rn(v - __half2float(hi));
    }
    size_t ne = (size_t)NLAYER * BB * KK;
    for (size_t idx = i; idx < ne; idx += stride) {
        int l = (int)(idx / (BB * KK));
        int r = (int)(idx % (BB * KK));
        float v = enc[idx];
        __half hi = __float2half_rn(v);
        g_h_hi[l][1][r] = hi;                       // parity 1 == h(t=-1)
        g_h_lo[l][1][r] = __float2half_rn(v - __half2float(hi));
    }
    if (i < NLAYER * NB) {
        ((unsigned int*)g_cnt)[i] = 0u;
    }
}

// ---------------- main persistent pipelined GRU kernel -----------------------
extern "C" __global__ void __launch_bounds__(NTHREADS, 1)
gru_main(const float* __restrict__ Wih, const float* __restrict__ Whh,
         const float* __restrict__ bih, const float* __restrict__ bhh,
         float* __restrict__ out) {
    extern __shared__ __half smem[];
    __half* sWih_hi = smem;                    // 48 x LDB
    __half* sWih_lo = smem + 1 * 48 * LDB;
    __half* sWhh_hi = smem + 2 * 48 * LDB;
    __half* sWhh_lo = smem + 3 * 48 * LDB;
    float*  stage   = (float*)(smem + 4 * 48 * LDB);  // 12 tiles of 16x20 fp32

    const int bid   = blockIdx.x;
    const int layer = bid >> 6;        // 0..1
    const int rem   = bid & 63;
    const int g     = rem >> 5;        // batch group 0..1
    const int cidx  = rem & 31;        // column CTA 0..31
    const int b0    = g * BC;
    const int tid   = threadIdx.x;
    const int wid   = tid >> 5;

    // ---- load + split this CTA's weight slice into SMEM (once) ----
    const float* WihL = Wih + (size_t)layer * G3 * KK;
    const float* WhhL = Whh + (size_t)layer * G3 * KK;
    for (int idx = tid; idx < 48 * KK; idx += NTHREADS) {
        int row = idx >> 9;            // 0..47 (gate*16 + r)
        int k   = idx & 511;
        int grow = (row >> 4) * 512 + cidx * 16 + (row & 15); // global gate row
        float v = WihL[(size_t)grow * KK + k];
        __half h = __float2half_rn(v);
        sWih_hi[row * LDB + k] = h;
        sWih_lo[row * LDB + k] = __float2half_rn(v - __half2float(h));
        v = WhhL[(size_t)grow * KK + k];
        h = __float2half_rn(v);
        sWhh_hi[row * LDB + k] = h;
        sWhh_lo[row * LDB + k] = __float2half_rn(v - __half2float(h));
    }
    __syncthreads();

    // job mapping: 12 warps = 2 row-blocks x {gi_r, gh_r, gi_z, gh_z, gi_n, gh_n}
    const int  rb    = wid / 6;        // 0..1 (16-row batch block)
    const int  jj    = wid % 6;
    const int  gate  = jj >> 1;        // 0=r 1=z 2=n
    const bool is_gi = (jj & 1) == 0;
    const __half* Bhi = (is_gi ? sWih_hi : sWhh_hi) + gate * 16 * LDB;
    const __half* Blo = (is_gi ? sWih_lo : sWhh_lo) + gate * 16 * LDB;

    volatile unsigned int* cnt0 = &g_cnt[0][g];
    volatile unsigned int* cnt1 = &g_cnt[1][g];

    // bias values for epilogue (cached per thread where used)
    for (int t = 0; t < TT; t++) {
        // ---- inter-CTA waits (producer/consumer + backpressure) ----
        if (tid == 0) {
            unsigned tgt0, tgt1;
            if (layer == 0) {
                tgt0 = (unsigned)(NC * t);                       // own layer done t-1
                tgt1 = (t >= 1) ? (unsigned)(NC * (t - 1)) : 0u; // layer1 done t-2
            } else {
                tgt0 = (unsigned)(NC * (t + 1));                 // h0(t) ready
                tgt1 = (unsigned)(NC * t);                       // own layer done t-1
            }
            while (*cnt0 < tgt0 || *cnt1 < tgt1) { __nanosleep(64); }
            __threadfence();
        }
        __syncthreads();

        // ---- A operand selection ----
        const __half *Ahi, *Alo;
        unsigned lda;
        if (layer == 0 && is_gi) {
            size_t off = ((size_t)b0 * TT + t) * KK;
            Ahi = g_x_hi + off;  Alo = g_x_lo + off;  lda = TT * KK;
        } else {
            int srcl = is_gi ? 0 : layer;                 // layer1 gi reads h0(t)
            int par  = is_gi ? (t & 1) : ((t + 1) & 1);   // gh reads h(t-1)
            Ahi = &g_h_hi[srcl][par][b0 * KK];
            Alo = &g_h_lo[srcl][par][b0 * KK];
            lda = KK;
        }
        Ahi += (size_t)rb * 16 * lda;
        Alo += (size_t)rb * 16 * lda;

        // ---- 3-pass fp16 GEMM: C[16x16] over K=512 ----
        wmma::fragment<wmma::accumulator, 16, 16, 16, float> acc;
        wmma::fill_fragment(acc, 0.0f);
        for (int k0 = 0; k0 < KK; k0 += 16) {
            wmma::fragment<wmma::matrix_a, 16, 16, 16, __half, wmma::row_major> ahi, alo;
            wmma::fragment<wmma::matrix_b, 16, 16, 16, __half, wmma::col_major> bhif, blof;
            wmma::load_matrix_sync(ahi,  Ahi + k0, lda);
            wmma::load_matrix_sync(alo,  Alo + k0, lda);
            wmma::load_matrix_sync(bhif, Bhi + k0, LDB);
            wmma::load_matrix_sync(blof, Blo + k0, LDB);
            wmma::mma_sync(acc, ahi, bhif, acc);   // hi*hi
            wmma::mma_sync(acc, alo, bhif, acc);   // lo*hi
            wmma::mma_sync(acc, ahi, blof, acc);   // hi*lo
        }
        wmma::store_matrix_sync(stage + wid * 16 * 20, acc, 20, wmma::mem_row_major);
        __syncthreads();

        // ---- epilogue: gates + state update for this CTA's 32x16 slice ----
        for (int e = tid; e < BC * HC; e += NTHREADS) {
            int row = e >> 4;            // 0..31 batch row in group
            int c   = e & 15;            // 0..15 local H col
            int rb2 = row >> 4;
            int rr  = row & 15;
            const float* st = stage + rb2 * 6 * 320;
            float giR = st[0 * 320 + rr * 20 + c];
            float ghR = st[1 * 320 + rr * 20 + c];
            float giZ = st[2 * 320 + rr * 20 + c];
            float ghZ = st[3 * 320 + rr * 20 + c];
            float giN = st[4 * 320 + rr * 20 + c];
            float ghN = st[5 * 320 + rr * 20 + c];

            int gc = cidx * 16 + c;                  // global H column
            const float* bihL = bih + layer * G3;
            const float* bhhL = bhh + layer * G3;
            float r = 1.0f / (1.0f + expf(-(giR + bihL[gc]        + ghR + bhhL[gc])));
            float z = 1.0f / (1.0f + expf(-(giZ + bihL[512 + gc]  + ghZ + bhhL[512 + gc])));
            float n = tanhf(giN + bihL[1024 + gc] + r * (ghN + bhhL[1024 + gc]));

            int hb = b0 + row;
            int pv = (t + 1) & 1;                    // parity of h(t-1)
            int hidx = hb * KK + gc;
            float hp = __half2float(g_h_hi[layer][pv][hidx]) +
                       __half2float(g_h_lo[layer][pv][hidx]);
            float hn = (1.0f - z) * n + z * hp;

            int pc = t & 1;                          // parity of h(t)
            __half hh = __float2half_rn(hn);
            g_h_hi[layer][pc][hidx] = hh;
            g_h_lo[layer][pc][hidx] = __float2half_rn(hn - __half2float(hh));

            if (layer == 1)
                out[((size_t)hb * TT + t) * KK + gc] = hn;
            if (t == TT - 1)
                out[(size_t)BB * TT * KK + (size_t)layer * BB * KK + hidx] = hn;
        }
        __threadfence();
        __syncthreads();
        if (tid == 0) {
            atomicAdd((unsigned int*)(layer == 0 ? cnt0 : cnt1), 1u);
        }
    }
}

// ---------------- launcher ---------------------------------------------------
extern "C" void kernel_launch(void* const* d_in, const int* in_sizes, int n_in,
                              void* d_out, int out_size) {
    const float* x   = (const float*)d_in[0];  // [B,T,IN]
    const float* enc = (const float*)d_in[1];  // [L,B,H]
    const float* Wih = (const float*)d_in[2];  // [L,3H,IN]
    const float* Whh = (const float*)d_in[3];  // [L,3H,H]
    const float* bih = (const float*)d_in[4];  // [L,3H]
    const float* bhh = (const float*)d_in[5];  // [L,3H]
    float* out = (float*)d_out;                // [B,T,H] ++ [L,B,H]

    (void)in_sizes; (void)n_in; (void)out_size;

    // 4 weight matrices split hi/lo + fp32 staging tiles
    size_t smem_bytes = (size_t)4 * 48 * LDB * sizeof(__half)
                      + (size_t)NWARP * 16 * 20 * sizeof(float); // 215,040 B
    cudaFuncSetAttribute(gru_main, cudaFuncAttributeMaxDynamicSharedMemorySize,
                         (int)smem_bytes);

    gru_prepass<<<2048, 256>>>(x, enc);
    gru_main<<<NLAYER * NC * NB, NTHREADS, smem_bytes>>>(Wih, Whh, bih, bhh, out);
}

// round 4
// speedup vs baseline: 1.2832x; 1.2824x over previous
#include <cuda_runtime.h>
#include <cuda_fp16.h>
#include <mma.h>

using namespace nvcuda;

#define BB   64
#define TT   512
#define KK   512
#define G3   1536
#define LDB  520
#define NTHREADS 384
#define SLD  20
#define TILE_F (16*SLD)

__device__ __half g_x_hi[(size_t)BB * TT * KK];
__device__ __half g_x_lo[(size_t)BB * TT * KK];
__device__ __half g_h_hi[2][2][BB * KK];
__device__ __half g_h_lo[2][2][BB * KK];
__device__ float  g_gi0[(size_t)TT * BB * G3];
__device__ unsigned int g_c0, g_c1tot, g_cg1[2];

__global__ void gru_prepass(const float* __restrict__ x,
                            const float* __restrict__ enc) {
    size_t i = (size_t)blockIdx.x * blockDim.x + threadIdx.x;
    size_t stride = (size_t)gridDim.x * blockDim.x;
    size_t n = (size_t)BB * TT * KK;
    for (size_t idx = i; idx < n; idx += stride) {
        float v = x[idx];
        __half hi = __float2half_rn(v);
        g_x_hi[idx] = hi;
        g_x_lo[idx] = __float2half_rn(v - __half2float(hi));
    }
    size_t ne = (size_t)2 * BB * KK;
    for (size_t idx = i; idx < ne; idx += stride) {
        int l = (int)(idx / (BB * KK));
        int r = (int)(idx % (BB * KK));
        float v = enc[idx];
        __half hi = __float2half_rn(v);
        g_h_hi[l][1][r] = hi;
        g_h_lo[l][1][r] = __float2half_rn(v - __half2float(hi));
    }
    if (i == 0) { g_c0 = 0; g_c1tot = 0; g_cg1[0] = 0; g_cg1[1] = 0; }
}

__device__ __forceinline__ void load_weights(const float* __restrict__ W,
                                             __half* shi, __half* slo, int cidx) {
    for (int idx = threadIdx.x; idx < 48 * KK; idx += NTHREADS) {
        int row = idx >> 9, k = idx & 511;
        int grow = (row >> 4) * 512 + cidx * 16 + (row & 15);
        float v = W[(size_t)grow * KK + k];
        __half h = __float2half_rn(v);
        shi[row * LDB + k] = h;
        slo[row * LDB + k] = __float2half_rn(v - __half2float(h));
    }
}

typedef wmma::fragment<wmma::accumulator, 16, 16, 16, float> AccFrag;

__device__ __forceinline__ void gemm3(const __half* Ahi, const __half* Alo,
                                      unsigned lda, const __half* Bhi,
                                      const __half* Blo, int k0, int k1,
                                      AccFrag acc[3]) {
    for (int kt = k0; kt < k1; ++kt) {
        wmma::fragment<wmma::matrix_a, 16, 16, 16, __half, wmma::row_major> ahi, alo;
        wmma::load_matrix_sync(ahi, Ahi + kt * 16, lda);
        wmma::load_matrix_sync(alo, Alo + kt * 16, lda);
#pragma unroll
        for (int gg = 0; gg < 3; gg++) {
            wmma::fragment<wmma::matrix_b, 16, 16, 16, __half, wmma::col_major> bh, bl;
            wmma::load_matrix_sync(bh, Bhi + gg * 16 * LDB + kt * 16, LDB);
            wmma::load_matrix_sync(bl, Blo + gg * 16 * LDB + kt * 16, LDB);
            wmma::mma_sync(acc[gg], ahi, bh, acc[gg]);
            wmma::mma_sync(acc[gg], alo, bh, acc[gg]);
            wmma::mma_sync(acc[gg], ahi, bl, acc[gg]);
        }
    }
}

__device__ __forceinline__ void reduce3(float* stage, int tilebase, int ks,
                                        AccFrag acc[3]) {
#pragma unroll
    for (int p = 0; p < 3; p++) {
        if (ks == p) {
#pragma unroll
            for (int gg = 0; gg < 3; gg++) {
                float* tp = stage + (tilebase + gg) * TILE_F;
                if (p > 0) {
                    AccFrag c;
                    wmma::load_matrix_sync(c, tp, SLD, wmma::mem_row_major);
                    for (int i = 0; i < c.num_elements; i++) acc[gg].x[i] += c.x[i];
                }
                wmma::store_matrix_sync(tp, acc[gg], SLD, wmma::mem_row_major);
            }
        }
        __syncthreads();
    }
}

__device__ __forceinline__ void spin_ge(volatile unsigned int* p, unsigned tgt) {
    while (*p < tgt) { __nanosleep(64); }
}

// bulk: gi0[t][b][3H] = x_t @ W_ih0^T + b_ih0  (no recurrence)
extern "C" __global__ void __launch_bounds__(NTHREADS, 1)
gru_bulk(const float* __restrict__ Wih, const float* __restrict__ bih) {
    extern __shared__ __half smem[];
    __half* shi = smem;
    __half* slo = smem + 48 * LDB;
    float*  stage = (float*)(smem + 2 * 48 * LDB);
    const int cidx = blockIdx.x & 31;
    const int tg   = blockIdx.x >> 5;
    const int tid  = threadIdx.x, wid = tid >> 5;
    const int rb = wid / 3, ks = wid % 3;
    const int k0 = ks * 11, k1 = (ks == 2) ? 32 : k0 + 11;

    load_weights(Wih, shi, slo, cidx);
    __syncthreads();

    for (int tt = 0; tt < 32; tt++) {
        int t = tg * 32 + tt;
        const __half* Ahi = g_x_hi + ((size_t)(rb * 16) * TT + t) * KK;
        const __half* Alo = g_x_lo + ((size_t)(rb * 16) * TT + t) * KK;
        AccFrag acc[3];
#pragma unroll
        for (int gg = 0; gg < 3; gg++) wmma::fill_fragment(acc[gg], 0.0f);
        gemm3(Ahi, Alo, (unsigned)(TT * KK), shi, slo, k0, k1, acc);
        reduce3(stage, rb * 3, ks, acc);
        for (int e = tid; e < 64 * 16; e += NTHREADS) {
            int row = e >> 4, c = e & 15, rb2 = row >> 4, rr = row & 15;
            int gc = cidx * 16 + c;
            const float* st = stage + rb2 * 3 * TILE_F;
            float* dst = &g_gi0[((size_t)t * BB + row) * G3];
            dst[gc]        = st[rr * SLD + c]              + bih[gc];
            dst[512 + gc]  = st[TILE_F + rr * SLD + c]     + bih[512 + gc];
            dst[1024 + gc] = st[2 * TILE_F + rr * SLD + c] + bih[1024 + gc];
        }
        __syncthreads();
    }
}

extern "C" __global__ void __launch_bounds__(NTHREADS, 1)
gru_main(const float* __restrict__ Wih, const float* __restrict__ Whh,
         const float* __restrict__ bih, const float* __restrict__ bhh,
         float* __restrict__ out) {
    extern __shared__ __half smem[];
    const int bid = blockIdx.x, tid = threadIdx.x;
    const int wid = tid >> 5, lane = tid & 31;
    const bool L0 = (bid < 32);

    __half *sWih_hi = nullptr, *sWih_lo = nullptr, *sWhh_hi, *sWhh_lo;
    float* stage;
    int cidx, grp = 0, b0 = 0, BC;

    if (L0) {
        cidx = bid; BC = 64;
        sWhh_hi = smem; sWhh_lo = smem + 48 * LDB;
        stage = (float*)(smem + 2 * 48 * LDB);
        load_weights(Whh, sWhh_hi, sWhh_lo, cidx);
    } else {
        int r = bid - 32;
        grp = r >> 5; cidx = r & 31; b0 = grp * 32; BC = 32;
        sWih_hi = smem;                sWih_lo = smem + 48 * LDB;
        sWhh_hi = smem + 2 * 48 * LDB; sWhh_lo = smem + 3 * 48 * LDB;
        stage = (float*)(smem + 4 * 48 * LDB);
        load_weights(Wih + (size_t)G3 * KK, sWih_hi, sWih_lo, cidx);
        load_weights(Whh + (size_t)G3 * KK, sWhh_hi, sWhh_lo, cidx);
    }
    __syncthreads();

    int srcid, rb, ks;
    if (L0) { srcid = 1; rb = wid / 3; ks = wid % 3; }
    else    { srcid = wid / 6; rb = (wid % 6) / 3; ks = wid % 3; }
    const int k0 = ks * 11, k1 = (ks == 2) ? 32 : k0 + 11;
    const int tilebase = L0 ? (rb * 3) : ((srcid * 2 + rb) * 3);
    const int layer = L0 ? 0 : 1;
    const float* bihL = bih + layer * G3;
    const float* bhhL = bhh + layer * G3;

    for (int t = 0; t < TT; t++) {
        if (lane == 0) {
            if (L0) {
                spin_ge(&g_c0, (unsigned)(32 * t));
                if (t >= 1) spin_ge(&g_c1tot, (unsigned)(64 * (t - 1)));
            } else if (srcid == 0) {
                spin_ge(&g_c0, (unsigned)(32 * (t + 1)));   // need h0(t)
            } else {
                spin_ge(&g_cg1[grp], (unsigned)(32 * t));   // need h1(t-1)
            }
        }
        __syncwarp();
        __threadfence();

        const __half *Ahi, *Alo;
        if (L0) {
            int pv = (t + 1) & 1;
            Ahi = &g_h_hi[0][pv][0] + rb * 16 * KK;
            Alo = &g_h_lo[0][pv][0] + rb * 16 * KK;
        } else if (srcid == 0) {
            int p = t & 1;
            Ahi = &g_h_hi[0][p][b0 * KK] + rb * 16 * KK;
            Alo = &g_h_lo[0][p][b0 * KK] + rb * 16 * KK;
        } else {
            int pv = (t + 1) & 1;
            Ahi = &g_h_hi[1][pv][b0 * KK] + rb * 16 * KK;
            Alo = &g_h_lo[1][pv][b0 * KK] + rb * 16 * KK;
        }
        const __half* Bh = (srcid == 0) ? sWih_hi : sWhh_hi;
        const __half* Bl = (srcid == 0) ? sWih_lo : sWhh_lo;

        AccFrag acc[3];
#pragma unroll
        for (int gg = 0; gg < 3; gg++) wmma::fill_fragment(acc[gg], 0.0f);
        gemm3(Ahi, Alo, KK, Bh, Bl, k0, k1, acc);
        reduce3(stage, tilebase, ks, acc);

        for (int e = tid; e < BC * 16; e += NTHREADS) {
            int row = e >> 4, c = e & 15, rb2 = row >> 4, rr = row & 15;
            int gc = cidx * 16 + c;
            float giR, giZ, giN, ghR, ghZ, ghN;
            if (L0) {
                const float* gi = &g_gi0[((size_t)t * BB + row) * G3];
                giR = gi[gc]; giZ = gi[512 + gc]; giN = gi[1024 + gc];
                const float* st = stage + rb2 * 3 * TILE_F;
                ghR = st[rr * SLD + c];
                ghZ = st[TILE_F + rr * SLD + c];
                ghN = st[2 * TILE_F + rr * SLD + c];
            } else {
                const float* sg = stage + rb2 * 3 * TILE_F;
                const float* sh = stage + (2 + rb2) * 3 * TILE_F;
                giR = sg[rr * SLD + c]              + bihL[gc];
                giZ = sg[TILE_F + rr * SLD + c]     + bihL[512 + gc];
                giN = sg[2 * TILE_F + rr * SLD + c] + bihL[1024 + gc];
                ghR = sh[rr * SLD + c];
                ghZ = sh[TILE_F + rr * SLD + c];
                ghN = sh[2 * TILE_F + rr * SLD + c];
            }
            float r = 1.0f / (1.0f + expf(-(giR + ghR + bhhL[gc])));
            float z = 1.0f / (1.0f + expf(-(giZ + ghZ + bhhL[512 + gc])));
            float n = tanhf(giN + r * (ghN + bhhL[1024 + gc]));

            int hb = b0 + row;
            int hidx = hb * KK + gc;
            int pv = (t + 1) & 1, pc = t & 1;
            float hp = __half2float(g_h_hi[layer][pv][hidx]) +
                       __half2float(g_h_lo[layer][pv][hidx]);
            float hn = (1.0f - z) * n + z * hp;
            __half hh = __float2half_rn(hn);
            g_h_hi[layer][pc][hidx] = hh;
            g_h_lo[layer][pc][hidx] = __float2half_rn(hn - __half2float(hh));

            if (!L0)
                out[((size_t)hb * TT + t) * KK + gc] = hn;
            if (t == TT - 1)
                out[(size_t)BB * TT * KK + (size_t)layer * BB * KK + hidx] = hn;
        }
        __threadfence();
        __syncthreads();
        if (tid == 0) {
            if (L0) atomicAdd(&g_c0, 1u);
            else { atomicAdd(&g_cg1[grp], 1u); atomicAdd(&g_c1tot, 1u); }
        }
    }
}

extern "C" void kernel_launch(void* const* d_in, const int* in_sizes, int n_in,
                              void* d_out, int out_size) {
    const float* x   = (const float*)d_in[0];
    const float* enc = (const float*)d_in[1];
    const float* Wih = (const float*)d_in[2];
    const float* Whh = (const float*)d_in[3];
    const float* bih = (const float*)d_in[4];
    const float* bhh = (const float*)d_in[5];
    float* out = (float*)d_out;
    (void)in_sizes; (void)n_in; (void)out_size;

    size_t smem_main = (size_t)4 * 48 * LDB * 2 + (size_t)12 * TILE_F * 4;
    size_t smem_bulk = (size_t)2 * 48 * LDB * 2 + (size_t)12 * TILE_F * 4;
    cudaFuncSetAttribute(gru_main, cudaFuncAttributeMaxDynamicSharedMemorySize,
                         (int)smem_main);
    cudaFuncSetAttribute(gru_bulk, cudaFuncAttributeMaxDynamicSharedMemorySize,
                         (int)smem_bulk);

    gru_prepass<<<2048, 256>>>(x, enc);
    gru_bulk<<<512, NTHREADS, smem_bulk>>>(Wih, bih);
    gru_main<<<96, NTHREADS, smem_main>>>(Wih, Whh, bih, bhh, out);
}